// round 6
// baseline (speedup 1.0000x reference)
#include <cuda_runtime.h>
#include <math.h>

typedef unsigned long long ull;

// Problem dims
constexpr int nB = 128;
constexpr int nS = 128;
constexpr int nV = 128;
constexpr int nH = 512;
constexpr int nL = 64;
constexpr int nG = 3 * nH;     // 1536
constexpr int NBLK = 128;      // persistent scan blocks (<= 148 SMs)

// ---- scratch (device globals; no allocations allowed) ----
__device__ float g_WT[2][nV * nG];            // W_ih transposed [d][v][g]
__device__ float g_xw[2ull * nS * nB * nG];   // [d][s][b][g]
__device__ float g_ys[2ull * nS * nH * nB];   // [d][s][i][b]
// h interleaved: [parity][d][k2][b][2]  (element j of pair k2 = h[2*k2+j][b])
__device__ float g_h[2][2][nH * nB];
__device__ unsigned g_count = 0;              // grid barrier arrivals
__device__ unsigned g_gen = 0;                // grid barrier generation

// ============================================================
// helpers
// ============================================================
__device__ __forceinline__ void fma2(ull& d, ull a, ull b) {
    asm("fma.rn.f32x2 %0, %1, %2, %0;" : "+l"(d) : "l"(a), "l"(b));
}
__device__ __forceinline__ void cpa16(unsigned dst, const void* src) {
    asm volatile("cp.async.cg.shared.global [%0], [%1], 16;" :: "r"(dst), "l"(src));
}
__device__ __forceinline__ void cpa_commit() {
    asm volatile("cp.async.commit_group;");
}
template <int N>
__device__ __forceinline__ void cpa_wait() {
    asm volatile("cp.async.wait_group %0;" :: "n"(N));
}
__device__ __forceinline__ void barx(int id) {
    asm volatile("bar.sync %0, 256;" :: "r"(id) : "memory");
}
__device__ __forceinline__ float sigf(float x) {
    return 1.f / (1.f + expf(-x));
}

// sense-counting grid barrier across NBLK co-resident blocks
__device__ __forceinline__ void grid_barrier(unsigned target) {
    __threadfence();
    __syncthreads();
    if (threadIdx.x == 0) {
        unsigned t = atomicAdd(&g_count, 1);
        if (t == NBLK - 1) {
            g_count = 0;
            __threadfence();
            atomicExch(&g_gen, target);
        } else {
            unsigned v;
            do {
                asm volatile("ld.volatile.global.u32 %0, [%1];" : "=r"(v) : "l"(&g_gen));
            } while (v != target);
            __threadfence();
        }
    }
    __syncthreads();
}

// ============================================================
// 1) Transpose W_ih (g,v) -> (v,g)
// ============================================================
__global__ void wt_kernel(const float* __restrict__ Wf,
                          const float* __restrict__ Wb) {
    int idx = blockIdx.x * 256 + threadIdx.x;
    if (idx >= 2 * nV * nG) return;
    int d = idx / (nV * nG);
    int rem = idx - d * (nV * nG);
    int v = rem / nG, g = rem - v * nG;
    const float* Wsrc = d ? Wb : Wf;
    g_WT[d][rem] = Wsrc[g * nV + v];
}

// ============================================================
// 2) Sparse input projection straight from chars (<=16 nnz per row)
// ============================================================
__global__ void __launch_bounds__(256) xwk(const int* __restrict__ chars,
                                           const float* __restrict__ forget,
                                           const float* __restrict__ bihf,
                                           const float* __restrict__ bihb) {
    extern __shared__ float sm[];
    float* Wv  = sm;                       // [128 v][128 g]
    float* swt = sm + 16384;               // [128 b][16]
    int*   sc  = (int*)(sm + 18432);       // [128 b][16]
    float* fp  = sm + 20480;               // forget powers [17]

    int gc = blockIdx.x, s = blockIdx.y, d = blockIdx.z;
    int tid = threadIdx.x;

    const float* WT = g_WT[d];
    for (int p = tid; p < 4096; p += 256) {
        int v = p >> 5, g4 = p & 31;
        *(float4*)&Wv[v * 128 + g4 * 4] =
            *(const float4*)&WT[(size_t)v * nG + gc * 128 + g4 * 4];
    }
    if (tid == 0) {
        float f = *forget;
        fp[0] = 1.f;
        for (int i = 1; i <= 16; i++) fp[i] = fp[i - 1] * f;
    }
    __syncthreads();
    if (tid < 128) {
        int b = tid;
        const int* cp = chars + ((size_t)b * nS + s) * 16;
        int c[16];
#pragma unroll
        for (int w = 0; w < 16; w++) c[w] = cp[w];
        int cnt = 0;
#pragma unroll
        for (int w = 15; w >= 0; w--) {
            bool nz = (c[w] != 0);
            swt[b * 16 + w] = nz ? fp[cnt] : 0.f;
            sc[b * 16 + w] = c[w];
            cnt += nz ? 1 : 0;
        }
    }
    __syncthreads();

    int gq = tid & 31, rp = tid >> 5;
    const float* bih = d ? bihb : bihf;
    float4 bias = *(const float4*)&bih[gc * 128 + gq * 4];
    for (int it = 0; it < 16; it++) {
        int b = it * 8 + rp;
        float a0 = bias.x, a1 = bias.y, a2 = bias.z, a3 = bias.w;
#pragma unroll
        for (int w = 0; w < 16; w++) {
            float ww = swt[b * 16 + w];
            int cc = sc[b * 16 + w];
            float4 wv = *(const float4*)&Wv[cc * 128 + gq * 4];
            a0 += ww * wv.x; a1 += ww * wv.y; a2 += ww * wv.z; a3 += ww * wv.w;
        }
        *(float4*)&g_xw[(((size_t)d * nS + s) * nB + b) * nG + gc * 128 + gq * 4] =
            make_float4(a0, a1, a2, a3);
    }
}

// ============================================================
// 3) Persistent bidirectional GRU scan — 512 threads, k-split warp groups.
//    Block = (d, i-chunk of 8). Warp w: kh=w>>3 (k-half), bh=(w>>2)&1
//    (batch half), rp=w&3 (row pair). Lane: 2 batches.
//    Each kh-group: own cp.async double-buffer + named barrier (1+kh).
//    kh=1 donates partials via smem; kh=0 computes gates.
// ============================================================
__global__ void __launch_bounds__(512, 1) scan_kernel(
    const float* __restrict__ Whf, const float* __restrict__ bhf,
    const float* __restrict__ Whb, const float* __restrict__ bhb,
    const int* __restrict__ lengths) {
    extern __shared__ float sm[];
    float* Wsm = sm;                       // [24 rows][512 k] (48 KB)
    float* hsf = sm + 12288;               // 4 x [32 k2][128 b][2] (128 KB)
    ull*   part = (ull*)(sm + 45056);      // [256 thr][12] partials (24 KB)
    int*   lensm = (int*)(sm + 51200);     // [128]
    unsigned* sbase = (unsigned*)(sm + 51328);

    int tid = threadIdx.x;
    int d = blockIdx.x >> 6, ic = blockIdx.x & 63, i0 = ic * 8;
    const float* Wh = d ? Whb : Whf;
    const float* bh_p = d ? bhb : bhf;

    // load 24 W rows (3 gates x 8 i) once, natural layout
    for (int p = tid; p < 3072; p += 512) {
        int row = p >> 7, q = p & 127;
        float4 v = *(const float4*)&Wh[((size_t)(row >> 3) * nH + i0 + (row & 7)) * nH + q * 4];
        *(float4*)&Wsm[row * 512 + q * 4] = v;
    }
    if (tid < 128) lensm[tid] = lengths[tid];
    if (tid == 0) {
        unsigned v;
        asm volatile("ld.volatile.global.u32 %0, [%1];" : "=r"(v) : "l"(&g_gen));
        *sbase = v;
    }
    // zero initial hidden state (parity 0), this block's k2 slice
    for (int p = tid; p < 1024; p += 512)
        g_h[0][d][(size_t)(i0 >> 1) * 256 + p] = 0.f;
    __syncthreads();
    unsigned base = *sbase;

    int w = tid >> 5, lane = tid & 31;
    int kh = w >> 3;              // k-half group
    int bhh = (w >> 2) & 1;       // batch half
    int rp = w & 3;               // row pair
    int r0 = rp * 2;
    int b0 = bhh * 64 + lane * 2;
    int i_a = i0 + r0, i_b = i_a + 1;
    float bR0 = bh_p[i_a], bR1 = bh_p[i_b];
    float bZ0 = bh_p[nH + i_a], bZ1 = bh_p[nH + i_b];
    float bN0 = bh_p[2 * nH + i_a], bN1 = bh_p[2 * nH + i_b];
    unsigned hsf_s = (unsigned)__cvta_generic_to_shared(hsf);
    int len0 = lensm[b0], len1 = lensm[b0 + 1];
    int ts = tid & 255;           // thread index within kh-group

    // weight row pointers [gate][ii], k-half offset folded in
    const float* wp[3][2];
#pragma unroll
    for (int g = 0; g < 3; g++)
#pragma unroll
        for (int ii = 0; ii < 2; ii++)
            wp[g][ii] = Wsm + ((g * 8 + r0 + ii) << 9) + kh * 256;

    grid_barrier(base + 1);

    for (int step = 0; step < nS; step++) {
        int par = step & 1;
        const float* hin = g_h[par][d];
        float* hout = g_h[par ^ 1][d];

        // --- epilogue inputs: per-thread early LDG (kh=0 only) ---
        float2 xg[3][2];
        float4 hold4;
        if (kh == 0) {
            int lenv[2] = { len0, len1 };
#pragma unroll
            for (int bs = 0; bs < 2; bs++) {
                int b = b0 + bs;
                int len = lenv[bs];
                int seff = d ? ((len - 1 - step) > 0 ? (len - 1 - step) : 0) : step;
                const float* bp = &g_xw[(((size_t)d * nS + seff) * nB + b) * nG + i0 + r0];
                xg[0][bs] = __ldcg((const float2*)bp);
                xg[1][bs] = __ldcg((const float2*)(bp + nH));
                xg[2][bs] = __ldcg((const float2*)(bp + 2 * nH));
            }
            hold4 = __ldcg((const float4*)&hin[(size_t)(i_a >> 1) * 256 + b0 * 2]);
        }

        // --- stage first chunk of this group (global chunk kh*4) ---
        {
            const float* src = hin + (size_t)(kh * 4) * 8192;
            unsigned dst = hsf_s + (unsigned)((kh * 2) * 8192 * 4);
#pragma unroll
            for (int q = 0; q < 8; q++) {
                int p = ts + q * 256;
                cpa16(dst + (unsigned)(p * 16), src + p * 4);
            }
            cpa_commit();
        }

        ull acc[3][2][2];
#pragma unroll
        for (int g = 0; g < 3; g++)
#pragma unroll
            for (int ii = 0; ii < 2; ii++)
#pragma unroll
                for (int bs = 0; bs < 2; bs++) acc[g][ii][bs] = 0ull;

        for (int c = 0; c < 4; c++) {
            cpa_wait<0>();
            barx(1 + kh);
            if (c < 3) {
                const float* src = hin + (size_t)(kh * 4 + c + 1) * 8192;
                unsigned dst = hsf_s + (unsigned)((kh * 2 + ((c + 1) & 1)) * 8192 * 4);
#pragma unroll
                for (int q = 0; q < 8; q++) {
                    int p = ts + q * 256;
                    cpa16(dst + (unsigned)(p * 16), src + p * 4);
                }
                cpa_commit();
            }
            const float* hb = hsf + (kh * 2 + (c & 1)) * 8192 + (b0 << 1);
            const float* pw00 = wp[0][0] + c * 64; const float* pw01 = wp[0][1] + c * 64;
            const float* pw10 = wp[1][0] + c * 64; const float* pw11 = wp[1][1] + c * 64;
            const float* pw20 = wp[2][0] + c * 64; const float* pw21 = wp[2][1] + c * 64;
#pragma unroll
            for (int t = 0; t < 16; t++) {
                ulonglong2 hA = *(const ulonglong2*)(hb + (t << 9));
                ulonglong2 hB = *(const ulonglong2*)(hb + (t << 9) + 256);
                ulonglong2 w0a = *(const ulonglong2*)(pw00 + (t << 2));
                ulonglong2 w0b = *(const ulonglong2*)(pw01 + (t << 2));
                fma2(acc[0][0][0], w0a.x, hA.x); fma2(acc[0][0][0], w0a.y, hB.x);
                fma2(acc[0][0][1], w0a.x, hA.y); fma2(acc[0][0][1], w0a.y, hB.y);
                fma2(acc[0][1][0], w0b.x, hA.x); fma2(acc[0][1][0], w0b.y, hB.x);
                fma2(acc[0][1][1], w0b.x, hA.y); fma2(acc[0][1][1], w0b.y, hB.y);
                ulonglong2 w1a = *(const ulonglong2*)(pw10 + (t << 2));
                ulonglong2 w1b = *(const ulonglong2*)(pw11 + (t << 2));
                fma2(acc[1][0][0], w1a.x, hA.x); fma2(acc[1][0][0], w1a.y, hB.x);
                fma2(acc[1][0][1], w1a.x, hA.y); fma2(acc[1][0][1], w1a.y, hB.y);
                fma2(acc[1][1][0], w1b.x, hA.x); fma2(acc[1][1][0], w1b.y, hB.x);
                fma2(acc[1][1][1], w1b.x, hA.y); fma2(acc[1][1][1], w1b.y, hB.y);
                ulonglong2 w2a = *(const ulonglong2*)(pw20 + (t << 2));
                ulonglong2 w2b = *(const ulonglong2*)(pw21 + (t << 2));
                fma2(acc[2][0][0], w2a.x, hA.x); fma2(acc[2][0][0], w2a.y, hB.x);
                fma2(acc[2][0][1], w2a.x, hA.y); fma2(acc[2][0][1], w2a.y, hB.y);
                fma2(acc[2][1][0], w2b.x, hA.x); fma2(acc[2][1][0], w2b.y, hB.x);
                fma2(acc[2][1][1], w2b.x, hA.y); fma2(acc[2][1][1], w2b.y, hB.y);
            }
            barx(1 + kh);
        }

        // --- kh=1 donates partials ---
        if (kh == 1) {
            ull* pp = part + (size_t)ts * 12;
#pragma unroll
            for (int g = 0; g < 3; g++)
#pragma unroll
                for (int ii = 0; ii < 2; ii++)
#pragma unroll
                    for (int bs = 0; bs < 2; bs++)
                        pp[g * 4 + ii * 2 + bs] = acc[g][ii][bs];
        }
        __syncthreads();

        if (kh == 0) {
            const ull* pp = part + (size_t)ts * 12;
            float sG[3][2][2];
#pragma unroll
            for (int g = 0; g < 3; g++)
#pragma unroll
                for (int ii = 0; ii < 2; ii++)
#pragma unroll
                    for (int bs = 0; bs < 2; bs++) {
                        float2 a = *(float2*)&acc[g][ii][bs];
                        ull pv = pp[g * 4 + ii * 2 + bs];
                        float2 p = *(float2*)&pv;
                        sG[g][ii][bs] = a.x + a.y + p.x + p.y;
                    }
            float bR[2] = { bR0, bR1 }, bZ[2] = { bZ0, bZ1 }, bN[2] = { bN0, bN1 };
            float holdv[2][2] = { { hold4.x, hold4.z }, { hold4.y, hold4.w } };
            bool msk[2] = { step < len0, step < len1 };
            float ho[2][2], yv[2][2];
#pragma unroll
            for (int ii = 0; ii < 2; ii++) {
#pragma unroll
                for (int bs = 0; bs < 2; bs++) {
                    float xr = ii ? xg[0][bs].y : xg[0][bs].x;
                    float xz = ii ? xg[1][bs].y : xg[1][bs].x;
                    float xn = ii ? xg[2][bs].y : xg[2][bs].x;
                    float hold = holdv[ii][bs];
                    float rg = sigf(xr + sG[0][ii][bs] + bR[ii]);
                    float zg = sigf(xz + sG[1][ii][bs] + bZ[ii]);
                    float ng = tanhf(xn + rg * (sG[2][ii][bs] + bN[ii]));
                    float hn = (1.f - zg) * ng + zg * hold;
                    ho[ii][bs] = msk[bs] ? hn : hold;
                    yv[ii][bs] = msk[bs] ? hn : 0.f;
                }
            }
            *(float4*)&hout[(size_t)(i_a >> 1) * 256 + b0 * 2] =
                make_float4(ho[0][0], ho[1][0], ho[0][1], ho[1][1]);
#pragma unroll
            for (int ii = 0; ii < 2; ii++)
                *(float2*)&g_ys[(((size_t)d * nS + step) * nH + i0 + r0 + ii) * nB + b0] =
                    make_float2(yv[ii][0], yv[ii][1]);
        }
        grid_barrier(base + 2 + step);
    }
}

// ============================================================
// 4) Output head (unchanged)
// ============================================================
__global__ void __launch_bounds__(256) out_kernel(
    const float* __restrict__ Wlin, const float* __restrict__ blin,
    const int* __restrict__ lengths, float* __restrict__ out) {
    __shared__ float As[64][64];
    __shared__ float Ws[64][65];
    __shared__ int lensm[64];
    int bh = blockIdx.x, s = blockIdx.y;
    int tid = threadIdx.x;
    if (tid < 64) lensm[tid] = lengths[bh * 64 + tid];
    int l = tid & 63, bg = tid >> 6;
    float acc[16];
#pragma unroll
    for (int j = 0; j < 16; j++) acc[j] = 0.f;

    for (int kc = 0; kc < 1024; kc += 64) {
        __syncthreads();
        if (kc < 512) {
            for (int p = tid; p < 1024; p += 256) {
                int kk = p >> 4, b4 = (p & 15) * 4;
                *(float4*)&As[kk][b4] = *(const float4*)
                    &g_ys[(((size_t)0 * nS + s) * nH + kc + kk) * nB + bh * 64 + b4];
            }
        } else {
            for (int p = tid; p < 4096; p += 256) {
                int kk = p >> 6, bb = p & 63;
                int b = bh * 64 + bb, len = lensm[bb];
                float v = 0.f;
                if (s < len) {
                    int t = len - 1 - s;
                    v = g_ys[(((size_t)1 * nS + t) * nH + (kc - 512 + kk)) * nB + b];
                }
                As[kk][bb] = v;
            }
        }
        for (int p = tid; p < 1024; p += 256) {
            int ll = p >> 4, k = (p & 15) * 4;
            float4 v = *(const float4*)&Wlin[(size_t)ll * 1024 + kc + k];
            Ws[k + 0][ll] = v.x; Ws[k + 1][ll] = v.y;
            Ws[k + 2][ll] = v.z; Ws[k + 3][ll] = v.w;
        }
        __syncthreads();
#pragma unroll 8
        for (int kk = 0; kk < 64; kk++) {
            float wv = Ws[kk][l];
            float4 h0 = *(float4*)&As[kk][bg * 16 + 0];
            float4 h1 = *(float4*)&As[kk][bg * 16 + 4];
            float4 h2 = *(float4*)&As[kk][bg * 16 + 8];
            float4 h3 = *(float4*)&As[kk][bg * 16 + 12];
            acc[0] += h0.x * wv; acc[1] += h0.y * wv; acc[2] += h0.z * wv; acc[3] += h0.w * wv;
            acc[4] += h1.x * wv; acc[5] += h1.y * wv; acc[6] += h1.z * wv; acc[7] += h1.w * wv;
            acc[8] += h2.x * wv; acc[9] += h2.y * wv; acc[10] += h2.z * wv; acc[11] += h2.w * wv;
            acc[12] += h3.x * wv; acc[13] += h3.y * wv; acc[14] += h3.z * wv; acc[15] += h3.w * wv;
        }
    }
    __syncthreads();
    float bias = blin[l];
#pragma unroll
    for (int j = 0; j < 16; j++) As[bg * 16 + j][l] = acc[j] + bias;
    __syncthreads();
    for (int p = tid; p < 1024; p += 256) {
        int bb = p >> 4, l4 = (p & 15) * 4;
        *(float4*)&out[(size_t)(bh * 64 + bb) * nS * nL + s * nL + l4] =
            *(float4*)&As[bb][l4];
    }
}

// ============================================================
extern "C" void kernel_launch(void* const* d_in, const int* in_sizes, int n_in,
                              void* d_out, int out_size) {
    const int*   chars   = (const int*)d_in[0];
    const int*   lengths = (const int*)d_in[1];
    const float* forget  = (const float*)d_in[2];
    const float* W_ih_f  = (const float*)d_in[3];
    const float* W_hh_f  = (const float*)d_in[4];
    const float* b_ih_f  = (const float*)d_in[5];
    const float* b_hh_f  = (const float*)d_in[6];
    const float* W_ih_b  = (const float*)d_in[7];
    const float* W_hh_b  = (const float*)d_in[8];
    const float* b_ih_b  = (const float*)d_in[9];
    const float* b_hh_b  = (const float*)d_in[10];
    const float* W_lin   = (const float*)d_in[11];
    const float* b_lin   = (const float*)d_in[12];
    float* out = (float*)d_out;

    cudaFuncSetAttribute(xwk, cudaFuncAttributeMaxDynamicSharedMemorySize, 90 * 1024);
    cudaFuncSetAttribute(scan_kernel, cudaFuncAttributeMaxDynamicSharedMemorySize, 210 * 1024);

    wt_kernel<<<(2 * nV * nG + 255) / 256, 256>>>(W_ih_f, W_ih_b);
    xwk<<<dim3(12, 128, 2), 256, 82000>>>(chars, forget, b_ih_f, b_ih_b);
    scan_kernel<<<NBLK, 512, 205828>>>(W_hh_f, b_hh_f, W_hh_b, b_hh_b, lengths);
    out_kernel<<<dim3(2, 128), 256>>>(W_lin, b_lin, lengths, out);
}

// round 9
// speedup vs baseline: 1.0419x; 1.0419x over previous
#include <cuda_runtime.h>
#include <math.h>

typedef unsigned long long ull;

// Problem dims
constexpr int nB = 128;
constexpr int nS = 128;
constexpr int nV = 128;
constexpr int nH = 512;
constexpr int nL = 64;
constexpr int nG = 3 * nH;     // 1536
constexpr int NBLK = 128;      // persistent scan blocks (<= 148 SMs)

// ---- scratch (device globals; no allocations allowed) ----
__device__ float g_WT[2][nV * nG];            // W_ih transposed [d][v][g]
__device__ float g_xw[2ull * nS * nB * nG];   // [d][s][b][g]
__device__ float g_ys[2ull * nS * nH * nB];   // [d][s][i][b]
// h double buffer, interleaved: [parity][d][k2][b][2]
__device__ float g_h[2][2][nH * nB];
__device__ unsigned g_cnt2[2] = {0, 0};       // per-direction barrier arrivals
__device__ unsigned g_gen2[2] = {0, 0};       // per-direction barrier generation

// ============================================================
// helpers
// ============================================================
__device__ __forceinline__ void fma2(ull& d, ull a, ull b) {
    asm("fma.rn.f32x2 %0, %1, %2, %0;" : "+l"(d) : "l"(a), "l"(b));
}
__device__ __forceinline__ void cpa16(unsigned dst, const void* src) {
    asm volatile("cp.async.cg.shared.global [%0], [%1], 16;" :: "r"(dst), "l"(src));
}
__device__ __forceinline__ void cpa_commit() {
    asm volatile("cp.async.commit_group;");
}
template <int N>
__device__ __forceinline__ void cpa_wait() {
    asm volatile("cp.async.wait_group %0;" :: "n"(N));
}
__device__ __forceinline__ void barh(int id) {   // half-block named barrier
    asm volatile("bar.sync %0, 128;" :: "r"(id) : "memory");
}
__device__ __forceinline__ float sigf(float x) {
    return 1.f / (1.f + expf(-x));
}

// per-direction sense barrier across 64 co-resident blocks
__device__ __forceinline__ void dir_barrier(int d, unsigned target) {
    __threadfence();
    __syncthreads();
    if (threadIdx.x == 0) {
        unsigned t = atomicAdd(&g_cnt2[d], 1);
        if (t == 63) {
            g_cnt2[d] = 0;
            __threadfence();
            atomicExch(&g_gen2[d], target);
        } else {
            unsigned v;
            do {
                asm volatile("ld.volatile.global.u32 %0, [%1];" : "=r"(v) : "l"(&g_gen2[d]));
            } while (v != target);
            __threadfence();
        }
    }
    __syncthreads();
}

// ============================================================
// 1) Transpose W_ih (g,v) -> (v,g)
// ============================================================
__global__ void wt_kernel(const float* __restrict__ Wf,
                          const float* __restrict__ Wb) {
    int idx = blockIdx.x * 256 + threadIdx.x;
    if (idx >= 2 * nV * nG) return;
    int d = idx / (nV * nG);
    int rem = idx - d * (nV * nG);
    int v = rem / nG, g = rem - v * nG;
    const float* Wsrc = d ? Wb : Wf;
    g_WT[d][rem] = Wsrc[g * nV + v];
}

// ============================================================
// 2) Sparse input projection straight from chars (<=16 nnz per row)
// ============================================================
__global__ void __launch_bounds__(256) xwk(const int* __restrict__ chars,
                                           const float* __restrict__ forget,
                                           const float* __restrict__ bihf,
                                           const float* __restrict__ bihb) {
    extern __shared__ float sm[];
    float* Wv  = sm;                       // [128 v][128 g]
    float* swt = sm + 16384;               // [128 b][16]
    int*   sc  = (int*)(sm + 18432);       // [128 b][16]
    float* fp  = sm + 20480;               // forget powers [17]

    int gc = blockIdx.x, s = blockIdx.y, d = blockIdx.z;
    int tid = threadIdx.x;

    const float* WT = g_WT[d];
    for (int p = tid; p < 4096; p += 256) {
        int v = p >> 5, g4 = p & 31;
        *(float4*)&Wv[v * 128 + g4 * 4] =
            *(const float4*)&WT[(size_t)v * nG + gc * 128 + g4 * 4];
    }
    if (tid == 0) {
        float f = *forget;
        fp[0] = 1.f;
        for (int i = 1; i <= 16; i++) fp[i] = fp[i - 1] * f;
    }
    __syncthreads();
    if (tid < 128) {
        int b = tid;
        const int* cp = chars + ((size_t)b * nS + s) * 16;
        int c[16];
#pragma unroll
        for (int w = 0; w < 16; w++) c[w] = cp[w];
        int cnt = 0;
#pragma unroll
        for (int w = 15; w >= 0; w--) {
            bool nz = (c[w] != 0);
            swt[b * 16 + w] = nz ? fp[cnt] : 0.f;
            sc[b * 16 + w] = c[w];
            cnt += nz ? 1 : 0;
        }
    }
    __syncthreads();

    int gq = tid & 31, rp = tid >> 5;
    const float* bih = d ? bihb : bihf;
    float4 bias = *(const float4*)&bih[gc * 128 + gq * 4];
    for (int it = 0; it < 16; it++) {
        int b = it * 8 + rp;
        float a0 = bias.x, a1 = bias.y, a2 = bias.z, a3 = bias.w;
#pragma unroll
        for (int w = 0; w < 16; w++) {
            float ww = swt[b * 16 + w];
            int cc = sc[b * 16 + w];
            float4 wv = *(const float4*)&Wv[cc * 128 + gq * 4];
            a0 += ww * wv.x; a1 += ww * wv.y; a2 += ww * wv.z; a3 += ww * wv.w;
        }
        *(float4*)&g_xw[(((size_t)d * nS + s) * nB + b) * nG + gc * 128 + gq * 4] =
            make_float4(a0, a1, a2, a3);
    }
}

// ============================================================
// 3) Persistent bidirectional GRU scan — per-direction barrier,
//    two independent 128-thread batch-halves with named barriers.
//    128 blocks: d = blk>>6, i-chunk of 8 = blk&63.
//    Warp w: bh = w>>2 (batch half), row pair r0 = 2*(w&3); lane: 2 batches.
//    Each half stages only its own 64-batch h slice (16 KB/chunk) into a
//    private 3-buffer ring; one named half-barrier per chunk.
// ============================================================
__global__ void __launch_bounds__(256, 1) scan_kernel(
    const float* __restrict__ Whf, const float* __restrict__ bhf,
    const float* __restrict__ Whb, const float* __restrict__ bhb,
    const int* __restrict__ lengths) {
    extern __shared__ float sm[];
    float* Wsm = sm;                     // [24 rows][512 k] (48 KB)
    float* hst = sm + 12288;             // 2 halves x 3 bufs x 4096 floats (96 KB)
    int*   lensm = (int*)(sm + 36864);   // [128]
    unsigned* sbase = (unsigned*)(sm + 36992);

    int tid = threadIdx.x;
    int d = blockIdx.x >> 6, ic = blockIdx.x & 63, i0 = ic * 8;
    const float* Wh = d ? Whb : Whf;
    const float* bh_p = d ? bhb : bhf;

    // load 24 W rows (3 gates x 8 i) once, natural layout
    for (int p = tid; p < 3072; p += 256) {
        int row = p >> 7, q = p & 127;
        float4 v = *(const float4*)&Wh[((size_t)(row >> 3) * nH + i0 + (row & 7)) * nH + q * 4];
        *(float4*)&Wsm[row * 512 + q * 4] = v;
    }
    if (tid < 128) lensm[tid] = lengths[tid];
    if (tid == 0) {
        unsigned v;
        asm volatile("ld.volatile.global.u32 %0, [%1];" : "=r"(v) : "l"(&g_gen2[d]));
        *sbase = v;
    }
    // zero initial hidden state (parity 0), this block's k2 slice
    for (int p = tid; p < 1024; p += 256)
        g_h[0][d][(size_t)(i0 >> 1) * 256 + p] = 0.f;
    __syncthreads();
    unsigned base = *sbase;
    dir_barrier(d, base + 1);

    int w = tid >> 5, lane = tid & 31;
    int bh = w >> 2;                      // batch half
    int r0 = (w & 3) * 2;
    int b0 = bh * 64 + lane * 2;
    int ts = tid & 127;                   // thread index within half
    int i_a = i0 + r0, i_b = i_a + 1;
    float bR0 = bh_p[i_a], bR1 = bh_p[i_b];
    float bZ0 = bh_p[nH + i_a], bZ1 = bh_p[nH + i_b];
    float bN0 = bh_p[2 * nH + i_a], bN1 = bh_p[2 * nH + i_b];
    float* hhalf = hst + bh * 12288;      // this half's 3-buffer ring
    unsigned hhalf_s = (unsigned)__cvta_generic_to_shared(hhalf);
    int len0 = lensm[b0], len1 = lensm[b0 + 1];
    int barid = 1 + bh;

    // per-warp weight row base pointers [gate][ii]
    const float* wp[3][2];
#pragma unroll
    for (int g = 0; g < 3; g++)
#pragma unroll
        for (int ii = 0; ii < 2; ii++)
            wp[g][ii] = Wsm + ((g * 8 + r0 + ii) << 9);

    for (int step = 0; step < nS; step++) {
        int par = step & 1;
        const float* hin = g_h[par][d];
        float* hout = g_h[par ^ 1][d];

        // --- epilogue inputs: per-thread early LDG (latency hidden by k-loop) ---
        float2 xg[3][2];
        float4 hold4;
        {
            int lenv[2] = { len0, len1 };
#pragma unroll
            for (int bs = 0; bs < 2; bs++) {
                int b = b0 + bs;
                int len = lenv[bs];
                int seff = d ? ((len - 1 - step) > 0 ? (len - 1 - step) : 0) : step;
                const float* bp = &g_xw[(((size_t)d * nS + seff) * nB + b) * nG + i0 + r0];
                xg[0][bs] = __ldcg((const float2*)bp);
                xg[1][bs] = __ldcg((const float2*)(bp + nH));
                xg[2][bs] = __ldcg((const float2*)(bp + 2 * nH));
            }
            hold4 = __ldcg((const float4*)&hin[(size_t)(i_a >> 1) * 256 + b0 * 2]);
        }

        // --- prologue: stage chunks 0 and 1 of this half's slice ---
#pragma unroll
        for (int cc = 0; cc < 2; cc++) {
            const float* src = hin + (size_t)cc * 8192 + bh * 128;
            unsigned dst = hhalf_s + (unsigned)(cc * 16384);
#pragma unroll
            for (int q = 0; q < 8; q++) {
                int lin = ts + q * 128;
                int k2 = lin >> 5, seg = lin & 31;
                cpa16(dst + (unsigned)((k2 * 128 + seg * 4) * 4),
                      src + (size_t)k2 * 256 + seg * 4);
            }
            cpa_commit();
        }

        // acc[g][ii][bs]: f32x2 (even-k, odd-k) partials
        ull acc[3][2][2];
#pragma unroll
        for (int g = 0; g < 3; g++)
#pragma unroll
            for (int ii = 0; ii < 2; ii++)
#pragma unroll
                for (int bs = 0; bs < 2; bs++) acc[g][ii][bs] = 0ull;

        for (int c = 0; c < 8; c++) {
            // wait for chunk c data (own groups), then half-barrier:
            // makes chunk c visible AND confirms all half-warps done with c-1
            if (c < 7) cpa_wait<1>(); else cpa_wait<0>();
            barh(barid);
            // stage chunk c+2 into buffer (c+2)%3 (now safe: c-1 consumers done)
            if (c < 6) {
                const float* src = hin + (size_t)(c + 2) * 8192 + bh * 128;
                unsigned dst = hhalf_s + (unsigned)(((c + 2) % 3) * 16384);
#pragma unroll
                for (int q = 0; q < 8; q++) {
                    int lin = ts + q * 128;
                    int k2 = lin >> 5, seg = lin & 31;
                    cpa16(dst + (unsigned)((k2 * 128 + seg * 4) * 4),
                          src + (size_t)k2 * 256 + seg * 4);
                }
                cpa_commit();
            }
            // compute chunk c
            const float* hb = hhalf + (c % 3) * 4096 + lane * 4;
            const float* pw00 = wp[0][0] + c * 64; const float* pw01 = wp[0][1] + c * 64;
            const float* pw10 = wp[1][0] + c * 64; const float* pw11 = wp[1][1] + c * 64;
            const float* pw20 = wp[2][0] + c * 64; const float* pw21 = wp[2][1] + c * 64;
#pragma unroll
            for (int t = 0; t < 16; t++) {
                ulonglong2 hA = *(const ulonglong2*)(hb + t * 256);        // k2'=2t
                ulonglong2 hB = *(const ulonglong2*)(hb + t * 256 + 128);  // k2'=2t+1
                ulonglong2 w0a = *(const ulonglong2*)(pw00 + (t << 2));
                ulonglong2 w0b = *(const ulonglong2*)(pw01 + (t << 2));
                fma2(acc[0][0][0], w0a.x, hA.x); fma2(acc[0][0][0], w0a.y, hB.x);
                fma2(acc[0][0][1], w0a.x, hA.y); fma2(acc[0][0][1], w0a.y, hB.y);
                fma2(acc[0][1][0], w0b.x, hA.x); fma2(acc[0][1][0], w0b.y, hB.x);
                fma2(acc[0][1][1], w0b.x, hA.y); fma2(acc[0][1][1], w0b.y, hB.y);
                ulonglong2 w1a = *(const ulonglong2*)(pw10 + (t << 2));
                ulonglong2 w1b = *(const ulonglong2*)(pw11 + (t << 2));
                fma2(acc[1][0][0], w1a.x, hA.x); fma2(acc[1][0][0], w1a.y, hB.x);
                fma2(acc[1][0][1], w1a.x, hA.y); fma2(acc[1][0][1], w1a.y, hB.y);
                fma2(acc[1][1][0], w1b.x, hA.x); fma2(acc[1][1][0], w1b.y, hB.x);
                fma2(acc[1][1][1], w1b.x, hA.y); fma2(acc[1][1][1], w1b.y, hB.y);
                ulonglong2 w2a = *(const ulonglong2*)(pw20 + (t << 2));
                ulonglong2 w2b = *(const ulonglong2*)(pw21 + (t << 2));
                fma2(acc[2][0][0], w2a.x, hA.x); fma2(acc[2][0][0], w2a.y, hB.x);
                fma2(acc[2][0][1], w2a.x, hA.y); fma2(acc[2][0][1], w2a.y, hB.y);
                fma2(acc[2][1][0], w2b.x, hA.x); fma2(acc[2][1][0], w2b.y, hB.x);
                fma2(acc[2][1][1], w2b.x, hA.y); fma2(acc[2][1][1], w2b.y, hB.y);
            }
        }
        // last chunk consumed; half-barrier before next step's staging happens
        // via dir_barrier below (full sync each step).

        // --- epilogue: fold partials, gates, store h(t+1) + ys ---
        float sG[3][2][2];
#pragma unroll
        for (int g = 0; g < 3; g++)
#pragma unroll
            for (int ii = 0; ii < 2; ii++)
#pragma unroll
                for (int bs = 0; bs < 2; bs++) {
                    float2 a = *(float2*)&acc[g][ii][bs];
                    sG[g][ii][bs] = a.x + a.y;
                }
        float bR[2] = { bR0, bR1 }, bZ[2] = { bZ0, bZ1 }, bN[2] = { bN0, bN1 };
        float holdv[2][2] = { { hold4.x, hold4.z }, { hold4.y, hold4.w } };
        bool msk[2] = { step < len0, step < len1 };
        float ho[2][2], yv[2][2];
#pragma unroll
        for (int ii = 0; ii < 2; ii++) {
#pragma unroll
            for (int bs = 0; bs < 2; bs++) {
                float xr = ii ? xg[0][bs].y : xg[0][bs].x;
                float xz = ii ? xg[1][bs].y : xg[1][bs].x;
                float xn = ii ? xg[2][bs].y : xg[2][bs].x;
                float hold = holdv[ii][bs];
                float rg = sigf(xr + sG[0][ii][bs] + bR[ii]);
                float zg = sigf(xz + sG[1][ii][bs] + bZ[ii]);
                float ng = tanhf(xn + rg * (sG[2][ii][bs] + bN[ii]));
                float hn = (1.f - zg) * ng + zg * hold;
                ho[ii][bs] = msk[bs] ? hn : hold;
                yv[ii][bs] = msk[bs] ? hn : 0.f;
            }
        }
        *(float4*)&hout[(size_t)(i_a >> 1) * 256 + b0 * 2] =
            make_float4(ho[0][0], ho[1][0], ho[0][1], ho[1][1]);
#pragma unroll
        for (int ii = 0; ii < 2; ii++)
            *(float2*)&g_ys[(((size_t)d * nS + step) * nH + i0 + r0 + ii) * nB + b0] =
                make_float2(yv[ii][0], yv[ii][1]);

        dir_barrier(d, base + 2 + step);
    }
}

// ============================================================
// 4) Output head (unchanged)
// ============================================================
__global__ void __launch_bounds__(256) out_kernel(
    const float* __restrict__ Wlin, const float* __restrict__ blin,
    const int* __restrict__ lengths, float* __restrict__ out) {
    __shared__ float As[64][64];
    __shared__ float Ws[64][65];
    __shared__ int lensm[64];
    int bh = blockIdx.x, s = blockIdx.y;
    int tid = threadIdx.x;
    if (tid < 64) lensm[tid] = lengths[bh * 64 + tid];
    int l = tid & 63, bg = tid >> 6;
    float acc[16];
#pragma unroll
    for (int j = 0; j < 16; j++) acc[j] = 0.f;

    for (int kc = 0; kc < 1024; kc += 64) {
        __syncthreads();
        if (kc < 512) {
            for (int p = tid; p < 1024; p += 256) {
                int kk = p >> 4, b4 = (p & 15) * 4;
                *(float4*)&As[kk][b4] = *(const float4*)
                    &g_ys[(((size_t)0 * nS + s) * nH + kc + kk) * nB + bh * 64 + b4];
            }
        } else {
            for (int p = tid; p < 4096; p += 256) {
                int kk = p >> 6, bb = p & 63;
                int b = bh * 64 + bb, len = lensm[bb];
                float v = 0.f;
                if (s < len) {
                    int t = len - 1 - s;
                    v = g_ys[(((size_t)1 * nS + t) * nH + (kc - 512 + kk)) * nB + b];
                }
                As[kk][bb] = v;
            }
        }
        for (int p = tid; p < 1024; p += 256) {
            int ll = p >> 4, k = (p & 15) * 4;
            float4 v = *(const float4*)&Wlin[(size_t)ll * 1024 + kc + k];
            Ws[k + 0][ll] = v.x; Ws[k + 1][ll] = v.y;
            Ws[k + 2][ll] = v.z; Ws[k + 3][ll] = v.w;
        }
        __syncthreads();
#pragma unroll 8
        for (int kk = 0; kk < 64; kk++) {
            float wv = Ws[kk][l];
            float4 h0 = *(float4*)&As[kk][bg * 16 + 0];
            float4 h1 = *(float4*)&As[kk][bg * 16 + 4];
            float4 h2 = *(float4*)&As[kk][bg * 16 + 8];
            float4 h3 = *(float4*)&As[kk][bg * 16 + 12];
            acc[0] += h0.x * wv; acc[1] += h0.y * wv; acc[2] += h0.z * wv; acc[3] += h0.w * wv;
            acc[4] += h1.x * wv; acc[5] += h1.y * wv; acc[6] += h1.z * wv; acc[7] += h1.w * wv;
            acc[8] += h2.x * wv; acc[9] += h2.y * wv; acc[10] += h2.z * wv; acc[11] += h2.w * wv;
            acc[12] += h3.x * wv; acc[13] += h3.y * wv; acc[14] += h3.z * wv; acc[15] += h3.w * wv;
        }
    }
    __syncthreads();
    float bias = blin[l];
#pragma unroll
    for (int j = 0; j < 16; j++) As[bg * 16 + j][l] = acc[j] + bias;
    __syncthreads();
    for (int p = tid; p < 1024; p += 256) {
        int bb = p >> 4, l4 = (p & 15) * 4;
        *(float4*)&out[(size_t)(bh * 64 + bb) * nS * nL + s * nL + l4] =
            *(float4*)&As[bb][l4];
    }
}

// ============================================================
extern "C" void kernel_launch(void* const* d_in, const int* in_sizes, int n_in,
                              void* d_out, int out_size) {
    const int*   chars   = (const int*)d_in[0];
    const int*   lengths = (const int*)d_in[1];
    const float* forget  = (const float*)d_in[2];
    const float* W_ih_f  = (const float*)d_in[3];
    const float* W_hh_f  = (const float*)d_in[4];
    const float* b_ih_f  = (const float*)d_in[5];
    const float* b_hh_f  = (const float*)d_in[6];
    const float* W_ih_b  = (const float*)d_in[7];
    const float* W_hh_b  = (const float*)d_in[8];
    const float* b_ih_b  = (const float*)d_in[9];
    const float* b_hh_b  = (const float*)d_in[10];
    const float* W_lin   = (const float*)d_in[11];
    const float* b_lin   = (const float*)d_in[12];
    float* out = (float*)d_out;

    cudaFuncSetAttribute(xwk, cudaFuncAttributeMaxDynamicSharedMemorySize, 90 * 1024);
    cudaFuncSetAttribute(scan_kernel, cudaFuncAttributeMaxDynamicSharedMemorySize, 152 * 1024);

    wt_kernel<<<(2 * nV * nG + 255) / 256, 256>>>(W_ih_f, W_ih_b);
    xwk<<<dim3(12, 128, 2), 256, 82000>>>(chars, forget, b_ih_f, b_ih_b);
    scan_kernel<<<NBLK, 256, 148000>>>(W_hh_f, b_hh_f, W_hh_b, b_hh_b, lengths);
    out_kernel<<<dim3(2, 128), 256>>>(W_lin, b_lin, lengths, out);
}